// round 3
// baseline (speedup 1.0000x reference)
#include <cuda_runtime.h>

// EMD approx-match (auction annealing), B=8, N=M=2048, 3-D points.
// Strategy: never materialize [B,N,M]; 3 fused O(N*M) passes per level:
//   pass1 (rowsum)  : s[n]  = sum_m exp(L*d2)*rR[m]
//   pass2 (colsum)  : ss[m] = sum_n w,  w = exp(L*d2)*rR[m]*rL[n]/(s[n]+eps)
//   pass3 (cost/rL) : ratio[m]=min(rR/(ss+eps),1); cost += w*ratio*dist;
//                     rL' = max(rL - sum_m w*ratio, 0)
//   rR' = max(rR - ratio*ss, 0)   (exact algebraic identity, folded into pass3 preproc)
// exp folded to a single ex2.approx per pair: t = q*d2 + lg2(factors), q = L*log2(e).
// Whole-warp ballot skip when exp underflows (annealing levels <= -64).

#define BB 8
#define NN 2048
#define MM 2048
#define EPSF 1e-9f
#define LOG2E 1.4426950408889634f
#define TMIN -126.0f

__device__ float g_s [BB * NN];
__device__ float g_ss[BB * MM];
__device__ float g_rL[2][BB * NN];
__device__ float g_rR[2][BB * MM];

__device__ __forceinline__ float lg2f(float x) {
    float r; asm("lg2.approx.f32 %0, %1;" : "=f"(r) : "f"(x)); return r;
}
__device__ __forceinline__ float ex2f(float x) {
    float r; asm("ex2.approx.f32 %0, %1;" : "=f"(r) : "f"(x)); return r;
}
__device__ __forceinline__ float sqrt_apx(float x) {
    float r; asm("sqrt.approx.f32 %0, %1;" : "=f"(r) : "f"(x)); return r;
}

__global__ void k_init(float* out) {
    int i = blockIdx.x * blockDim.x + threadIdx.x;
    if (i < BB * NN) { g_rL[0][i] = 1.0f; g_rR[0][i] = 1.0f; }
    if (i < BB) out[i] = 0.0f;
}

// ---------------- pass 1: row sums s[b][n] ----------------
template <bool SPARSE>
__global__ void __launch_bounds__(256, 1)
k_rowsum(const float* __restrict__ x1, const float* __restrict__ x2,
         int src, float q) {
    __shared__ float4 tile[MM];
    __shared__ float  red[256];
    const int b   = blockIdx.y;
    const int tid = threadIdx.x;
    const float n2q = -2.0f * q;
    const float* __restrict__ rR = g_rR[src] + b * MM;

    for (int j = tid; j < MM; j += 256) {
        const float* yp = x2 + ((size_t)b * MM + j) * 3;
        float y0 = yp[0], y1 = yp[1], y2 = yp[2];
        float c  = fmaf(q, fmaf(y0, y0, fmaf(y1, y1, y2 * y2)), lg2f(rR[j]));
        tile[j] = make_float4(n2q * y0, n2q * y1, n2q * y2, c);
    }
    __syncthreads();

    const int r  = blockIdx.x * 128 + (tid & 127);
    const int m0 = (tid >> 7) * (MM / 2);
    const float* xp = x1 + ((size_t)b * NN + r) * 3;
    float X0 = xp[0], X1 = xp[1], X2 = xp[2];
    float a  = q * fmaf(X0, X0, fmaf(X1, X1, X2 * X2));

    float s0 = 0.f, s1 = 0.f, s2 = 0.f, s3 = 0.f;
#pragma unroll 2
    for (int m = m0; m < m0 + MM / 2; m += 4) {
        float4 P0 = tile[m + 0], P1 = tile[m + 1], P2 = tile[m + 2], P3 = tile[m + 3];
        float t0 = fmaf(X0, P0.x, fmaf(X1, P0.y, fmaf(X2, P0.z, a + P0.w)));
        float t1 = fmaf(X0, P1.x, fmaf(X1, P1.y, fmaf(X2, P1.z, a + P1.w)));
        float t2 = fmaf(X0, P2.x, fmaf(X1, P2.y, fmaf(X2, P2.z, a + P2.w)));
        float t3 = fmaf(X0, P3.x, fmaf(X1, P3.y, fmaf(X2, P3.z, a + P3.w)));
        bool go = true;
        if (SPARSE) {
            float tm = fmaxf(fmaxf(t0, t1), fmaxf(t2, t3));
            go = __ballot_sync(0xffffffffu, tm > TMIN) != 0u;
        }
        if (go) {
            s0 += ex2f(t0); s1 += ex2f(t1); s2 += ex2f(t2); s3 += ex2f(t3);
        }
    }
    red[tid] = (s0 + s1) + (s2 + s3);
    __syncthreads();
    if (tid < 128) g_s[(size_t)b * NN + r] = red[tid] + red[tid + 128];
}

// ---------------- pass 2: column sums ss[b][m] ----------------
template <bool SPARSE>
__global__ void __launch_bounds__(256, 1)
k_colsum(const float* __restrict__ x1, const float* __restrict__ x2,
         int src, float q) {
    __shared__ float4 tile[NN];
    __shared__ float  red[256];
    const int b   = blockIdx.y;
    const int tid = threadIdx.x;
    const float n2q = -2.0f * q;

    for (int j = tid; j < NN; j += 256) {
        const float* xp = x1 + ((size_t)b * NN + j) * 3;
        float a0 = xp[0], a1 = xp[1], a2 = xp[2];
        float rl = g_rL[src][(size_t)b * NN + j];
        float sv = g_s[(size_t)b * NN + j];
        float f  = __fdividef(rl, sv + EPSF);
        float aj = fmaf(q, fmaf(a0, a0, fmaf(a1, a1, a2 * a2)), lg2f(f));
        tile[j] = make_float4(n2q * a0, n2q * a1, n2q * a2, aj);
    }
    __syncthreads();

    const int mcol = blockIdx.x * 128 + (tid & 127);
    const int n0   = (tid >> 7) * (NN / 2);
    const float* yp = x2 + ((size_t)b * MM + mcol) * 3;
    float Y0 = yp[0], Y1 = yp[1], Y2 = yp[2];
    float c  = fmaf(q, fmaf(Y0, Y0, fmaf(Y1, Y1, Y2 * Y2)),
                    lg2f(g_rR[src][(size_t)b * MM + mcol]));

    float s0 = 0.f, s1 = 0.f, s2 = 0.f, s3 = 0.f;
#pragma unroll 2
    for (int n = n0; n < n0 + NN / 2; n += 4) {
        float4 P0 = tile[n + 0], P1 = tile[n + 1], P2 = tile[n + 2], P3 = tile[n + 3];
        float t0 = fmaf(Y0, P0.x, fmaf(Y1, P0.y, fmaf(Y2, P0.z, c + P0.w)));
        float t1 = fmaf(Y0, P1.x, fmaf(Y1, P1.y, fmaf(Y2, P1.z, c + P1.w)));
        float t2 = fmaf(Y0, P2.x, fmaf(Y1, P2.y, fmaf(Y2, P2.z, c + P2.w)));
        float t3 = fmaf(Y0, P3.x, fmaf(Y1, P3.y, fmaf(Y2, P3.z, c + P3.w)));
        bool go = true;
        if (SPARSE) {
            float tm = fmaxf(fmaxf(t0, t1), fmaxf(t2, t3));
            go = __ballot_sync(0xffffffffu, tm > TMIN) != 0u;
        }
        if (go) {
            s0 += ex2f(t0); s1 += ex2f(t1); s2 += ex2f(t2); s3 += ex2f(t3);
        }
    }
    red[tid] = (s0 + s1) + (s2 + s3);
    __syncthreads();
    if (tid < 128) g_ss[(size_t)b * MM + mcol] = red[tid] + red[tid + 128];
}

// ---------------- pass 3: cost accumulation + rL update (+ rR update in preproc) ----------------
template <bool SPARSE>
__global__ void __launch_bounds__(256, 1)
k_pass3(const float* __restrict__ x1, const float* __restrict__ x2,
        int src, int dst, float q, float* __restrict__ out) {
    __shared__ float4 tile[MM];
    __shared__ float  red[256];
    __shared__ float  cred[256];
    const int b   = blockIdx.y;
    const int tid = threadIdx.x;
    const float* __restrict__ rR  = g_rR[src] + b * MM;
    float*       __restrict__ rRn = g_rR[dst] + b * MM;
    const float* __restrict__ ssp = g_ss + b * MM;

    for (int j = tid; j < MM; j += 256) {
        const float* yp = x2 + ((size_t)b * MM + j) * 3;
        float y0 = yp[0], y1 = yp[1], y2 = yp[2];
        float rr  = rR[j];
        float ssv = ssp[j];
        float ratio = fminf(__fdividef(rr, ssv + EPSF), 1.0f);
        tile[j] = make_float4(y0, y1, y2, lg2f(rr * ratio));
        // exact identity: sum_n w' = ratio*ss  -> rR update needs no pair pass
        if (blockIdx.x == 0) rRn[j] = fmaxf(rr - ratio * ssv, 0.0f);
    }
    __syncthreads();

    const int r  = blockIdx.x * 128 + (tid & 127);
    const int m0 = (tid >> 7) * (MM / 2);
    const float* xp = x1 + ((size_t)b * NN + r) * 3;
    float X0 = xp[0], X1 = xp[1], X2 = xp[2];
    float rl = g_rL[src][(size_t)b * NN + r];
    float sv = g_s[(size_t)b * NN + r];
    float base = lg2f(__fdividef(rl, sv + EPSF));

    float rs0 = 0.f, rs1 = 0.f, c0 = 0.f, c1 = 0.f;
#pragma unroll 2
    for (int m = m0; m < m0 + MM / 2; m += 2) {
        float4 P0 = tile[m + 0], P1 = tile[m + 1];
        float dx0 = X0 - P0.x, dy0 = X1 - P0.y, dz0 = X2 - P0.z;
        float dx1 = X0 - P1.x, dy1 = X1 - P1.y, dz1 = X2 - P1.z;
        float d20 = fmaf(dx0, dx0, fmaf(dy0, dy0, dz0 * dz0));
        float d21 = fmaf(dx1, dx1, fmaf(dy1, dy1, dz1 * dz1));
        float t0 = fmaf(d20, q, base + P0.w);
        float t1 = fmaf(d21, q, base + P1.w);
        bool go = true;
        if (SPARSE) {
            go = __ballot_sync(0xffffffffu, fmaxf(t0, t1) > TMIN) != 0u;
        }
        if (go) {
            float w0 = ex2f(t0), w1 = ex2f(t1);
            rs0 += w0; rs1 += w1;
            c0 = fmaf(w0, sqrt_apx(fmaxf(d20, 1e-20f)), c0);
            c1 = fmaf(w1, sqrt_apx(fmaxf(d21, 1e-20f)), c1);
        }
    }
    red[tid]  = rs0 + rs1;
    cred[tid] = c0 + c1;
    __syncthreads();
    if (tid < 128)
        g_rL[dst][(size_t)b * NN + r] = fmaxf(rl - (red[tid] + red[tid + 128]), 0.0f);
    for (int off = 128; off > 0; off >>= 1) {
        if (tid < off) cred[tid] += cred[tid + off];
        __syncthreads();
    }
    if (tid == 0) atomicAdd(&out[b], cred[0]);
}

extern "C" void kernel_launch(void* const* d_in, const int* in_sizes, int n_in,
                              void* d_out, int out_size) {
    const float* x1 = (const float*)d_in[0];  // input1 [B,N,3]
    const float* x2 = (const float*)d_in[1];  // input2 [B,M,3]
    float* out = (float*)d_out;               // [B] float32

    k_init<<<(BB * NN + 255) / 256, 256>>>(out);

    static const float levels[10] = {
        -16384.f, -4096.f, -1024.f, -256.f, -64.f, -16.f, -4.f, -1.f, -0.25f, 0.f
    };

    dim3 grid(16, BB);
    int cur = 0;
    for (int i = 0; i < 10; i++) {
        float q = levels[i] * LOG2E;
        bool sp = (levels[i] <= -64.0f);
        if (sp) {
            k_rowsum<true><<<grid, 256>>>(x1, x2, cur, q);
            k_colsum<true><<<grid, 256>>>(x1, x2, cur, q);
            k_pass3 <true><<<grid, 256>>>(x1, x2, cur, cur ^ 1, q, out);
        } else {
            k_rowsum<false><<<grid, 256>>>(x1, x2, cur, q);
            k_colsum<false><<<grid, 256>>>(x1, x2, cur, q);
            k_pass3 <false><<<grid, 256>>>(x1, x2, cur, cur ^ 1, q, out);
        }
        cur ^= 1;
    }
}

// round 4
// speedup vs baseline: 1.4547x; 1.4547x over previous
#include <cuda_runtime.h>

// EMD approx-match (auction annealing), B=8, N=M=2048, 3-D points.
// 3 fused O(N*M) passes per level; no [B,N,M] materialization.
// R3 change: 1024-thread CTAs (8 threads/row x 256 cols) to lift occupancy
// 12.4% -> ~50%; shuffle-based cost reduction.

#define BB 8
#define NN 2048
#define MM 2048
#define EPSF 1e-9f
#define LOG2E 1.4426950408889634f
#define TMIN -126.0f

#define NT   1024          // threads per CTA
#define RPC  128           // rows per CTA
#define SEGS 8             // column segments per row
#define SEGL (MM / SEGS)   // 256 columns per thread

__device__ float g_s [BB * NN];
__device__ float g_ss[BB * MM];
__device__ float g_rL[2][BB * NN];
__device__ float g_rR[2][BB * MM];

__device__ __forceinline__ float lg2f(float x) {
    float r; asm("lg2.approx.f32 %0, %1;" : "=f"(r) : "f"(x)); return r;
}
__device__ __forceinline__ float ex2f(float x) {
    float r; asm("ex2.approx.f32 %0, %1;" : "=f"(r) : "f"(x)); return r;
}
__device__ __forceinline__ float sqrt_apx(float x) {
    float r; asm("sqrt.approx.f32 %0, %1;" : "=f"(r) : "f"(x)); return r;
}

__global__ void k_init(float* out) {
    int i = blockIdx.x * blockDim.x + threadIdx.x;
    if (i < BB * NN) { g_rL[0][i] = 1.0f; g_rR[0][i] = 1.0f; }
    if (i < BB) out[i] = 0.0f;
}

// ---------------- pass 1: row sums s[b][n] ----------------
template <bool SPARSE>
__global__ void __launch_bounds__(NT, 1)
k_rowsum(const float* __restrict__ x1, const float* __restrict__ x2,
         int src, float q) {
    __shared__ float4 tile[MM];
    __shared__ float  red[NT];
    const int b   = blockIdx.y;
    const int tid = threadIdx.x;
    const float n2q = -2.0f * q;
    const float* __restrict__ rR = g_rR[src] + b * MM;

    for (int j = tid; j < MM; j += NT) {
        const float* yp = x2 + ((size_t)b * MM + j) * 3;
        float y0 = yp[0], y1 = yp[1], y2 = yp[2];
        float c  = fmaf(q, fmaf(y0, y0, fmaf(y1, y1, y2 * y2)), lg2f(rR[j]));
        tile[j] = make_float4(n2q * y0, n2q * y1, n2q * y2, c);
    }
    __syncthreads();

    const int r  = blockIdx.x * RPC + (tid & (RPC - 1));
    const int m0 = (tid >> 7) * SEGL;
    const float* xp = x1 + ((size_t)b * NN + r) * 3;
    float X0 = xp[0], X1 = xp[1], X2 = xp[2];
    float a  = q * fmaf(X0, X0, fmaf(X1, X1, X2 * X2));

    float s0 = 0.f, s1 = 0.f, s2 = 0.f, s3 = 0.f;
#pragma unroll 4
    for (int m = m0; m < m0 + SEGL; m += 4) {
        float4 P0 = tile[m + 0], P1 = tile[m + 1], P2 = tile[m + 2], P3 = tile[m + 3];
        float t0 = fmaf(X0, P0.x, fmaf(X1, P0.y, fmaf(X2, P0.z, a + P0.w)));
        float t1 = fmaf(X0, P1.x, fmaf(X1, P1.y, fmaf(X2, P1.z, a + P1.w)));
        float t2 = fmaf(X0, P2.x, fmaf(X1, P2.y, fmaf(X2, P2.z, a + P2.w)));
        float t3 = fmaf(X0, P3.x, fmaf(X1, P3.y, fmaf(X2, P3.z, a + P3.w)));
        bool go = true;
        if (SPARSE) {
            float tm = fmaxf(fmaxf(t0, t1), fmaxf(t2, t3));
            go = __ballot_sync(0xffffffffu, tm > TMIN) != 0u;
        }
        if (go) {
            s0 += ex2f(t0); s1 += ex2f(t1); s2 += ex2f(t2); s3 += ex2f(t3);
        }
    }
    red[tid] = (s0 + s1) + (s2 + s3);
    __syncthreads();
    if (tid < RPC) {
        float v = 0.f;
#pragma unroll
        for (int k = 0; k < SEGS; k++) v += red[tid + (k << 7)];
        g_s[(size_t)b * NN + blockIdx.x * RPC + tid] = v;
    }
}

// ---------------- pass 2: column sums ss[b][m] ----------------
template <bool SPARSE>
__global__ void __launch_bounds__(NT, 1)
k_colsum(const float* __restrict__ x1, const float* __restrict__ x2,
         int src, float q) {
    __shared__ float4 tile[NN];
    __shared__ float  red[NT];
    const int b   = blockIdx.y;
    const int tid = threadIdx.x;
    const float n2q = -2.0f * q;

    for (int j = tid; j < NN; j += NT) {
        const float* xp = x1 + ((size_t)b * NN + j) * 3;
        float a0 = xp[0], a1 = xp[1], a2 = xp[2];
        float rl = g_rL[src][(size_t)b * NN + j];
        float sv = g_s[(size_t)b * NN + j];
        float f  = __fdividef(rl, sv + EPSF);
        float aj = fmaf(q, fmaf(a0, a0, fmaf(a1, a1, a2 * a2)), lg2f(f));
        tile[j] = make_float4(n2q * a0, n2q * a1, n2q * a2, aj);
    }
    __syncthreads();

    const int mcol = blockIdx.x * RPC + (tid & (RPC - 1));
    const int n0   = (tid >> 7) * SEGL;
    const float* yp = x2 + ((size_t)b * MM + mcol) * 3;
    float Y0 = yp[0], Y1 = yp[1], Y2 = yp[2];
    float c  = fmaf(q, fmaf(Y0, Y0, fmaf(Y1, Y1, Y2 * Y2)),
                    lg2f(g_rR[src][(size_t)b * MM + mcol]));

    float s0 = 0.f, s1 = 0.f, s2 = 0.f, s3 = 0.f;
#pragma unroll 4
    for (int n = n0; n < n0 + SEGL; n += 4) {
        float4 P0 = tile[n + 0], P1 = tile[n + 1], P2 = tile[n + 2], P3 = tile[n + 3];
        float t0 = fmaf(Y0, P0.x, fmaf(Y1, P0.y, fmaf(Y2, P0.z, c + P0.w)));
        float t1 = fmaf(Y0, P1.x, fmaf(Y1, P1.y, fmaf(Y2, P1.z, c + P1.w)));
        float t2 = fmaf(Y0, P2.x, fmaf(Y1, P2.y, fmaf(Y2, P2.z, c + P2.w)));
        float t3 = fmaf(Y0, P3.x, fmaf(Y1, P3.y, fmaf(Y2, P3.z, c + P3.w)));
        bool go = true;
        if (SPARSE) {
            float tm = fmaxf(fmaxf(t0, t1), fmaxf(t2, t3));
            go = __ballot_sync(0xffffffffu, tm > TMIN) != 0u;
        }
        if (go) {
            s0 += ex2f(t0); s1 += ex2f(t1); s2 += ex2f(t2); s3 += ex2f(t3);
        }
    }
    red[tid] = (s0 + s1) + (s2 + s3);
    __syncthreads();
    if (tid < RPC) {
        float v = 0.f;
#pragma unroll
        for (int k = 0; k < SEGS; k++) v += red[tid + (k << 7)];
        g_ss[(size_t)b * MM + blockIdx.x * RPC + tid] = v;
    }
}

// ---------------- pass 3: cost + rL update (+ rR update in preproc) ----------------
template <bool SPARSE>
__global__ void __launch_bounds__(NT, 1)
k_pass3(const float* __restrict__ x1, const float* __restrict__ x2,
        int src, int dst, float q, float* __restrict__ out) {
    __shared__ float4 tile[MM];
    __shared__ float  red[NT];
    __shared__ float  cwarp[NT / 32];
    const int b   = blockIdx.y;
    const int tid = threadIdx.x;
    const int lane = tid & 31;
    const int wid  = tid >> 5;
    const float* __restrict__ rR  = g_rR[src] + b * MM;
    float*       __restrict__ rRn = g_rR[dst] + b * MM;
    const float* __restrict__ ssp = g_ss + b * MM;

    for (int j = tid; j < MM; j += NT) {
        const float* yp = x2 + ((size_t)b * MM + j) * 3;
        float y0 = yp[0], y1 = yp[1], y2 = yp[2];
        float rr  = rR[j];
        float ssv = ssp[j];
        float ratio = fminf(__fdividef(rr, ssv + EPSF), 1.0f);
        tile[j] = make_float4(y0, y1, y2, lg2f(rr * ratio));
        // exact identity: sum_n w' = ratio*ss -> rR update needs no pair pass
        if (blockIdx.x == 0) rRn[j] = fmaxf(rr - ratio * ssv, 0.0f);
    }
    __syncthreads();

    const int r  = blockIdx.x * RPC + (tid & (RPC - 1));
    const int m0 = (tid >> 7) * SEGL;
    const float* xp = x1 + ((size_t)b * NN + r) * 3;
    float X0 = xp[0], X1 = xp[1], X2 = xp[2];
    float rl = g_rL[src][(size_t)b * NN + r];
    float sv = g_s[(size_t)b * NN + r];
    float base = lg2f(__fdividef(rl, sv + EPSF));

    float rs0 = 0.f, rs1 = 0.f, c0 = 0.f, c1 = 0.f;
#pragma unroll 2
    for (int m = m0; m < m0 + SEGL; m += 2) {
        float4 P0 = tile[m + 0], P1 = tile[m + 1];
        float dx0 = X0 - P0.x, dy0 = X1 - P0.y, dz0 = X2 - P0.z;
        float dx1 = X0 - P1.x, dy1 = X1 - P1.y, dz1 = X2 - P1.z;
        float d20 = fmaf(dx0, dx0, fmaf(dy0, dy0, dz0 * dz0));
        float d21 = fmaf(dx1, dx1, fmaf(dy1, dy1, dz1 * dz1));
        float t0 = fmaf(d20, q, base + P0.w);
        float t1 = fmaf(d21, q, base + P1.w);
        bool go = true;
        if (SPARSE) {
            go = __ballot_sync(0xffffffffu, fmaxf(t0, t1) > TMIN) != 0u;
        }
        if (go) {
            float w0 = ex2f(t0), w1 = ex2f(t1);
            rs0 += w0; rs1 += w1;
            c0 = fmaf(w0, sqrt_apx(fmaxf(d20, 1e-20f)), c0);
            c1 = fmaf(w1, sqrt_apx(fmaxf(d21, 1e-20f)), c1);
        }
    }

    // rL update: 8 segment partials per row, summed by 128 threads
    red[tid] = rs0 + rs1;
    // cost: warp shuffle reduce, then cross-warp
    float c = c0 + c1;
#pragma unroll
    for (int off = 16; off > 0; off >>= 1)
        c += __shfl_down_sync(0xffffffffu, c, off);
    if (lane == 0) cwarp[wid] = c;
    __syncthreads();

    if (tid < RPC) {
        float v = 0.f;
#pragma unroll
        for (int k = 0; k < SEGS; k++) v += red[tid + (k << 7)];
        float rl0 = g_rL[src][(size_t)b * NN + blockIdx.x * RPC + tid];
        g_rL[dst][(size_t)b * NN + blockIdx.x * RPC + tid] = fmaxf(rl0 - v, 0.0f);
    }
    if (wid == 0) {
        float v = cwarp[lane];  // NT/32 == 32 warps -> exactly one value per lane
#pragma unroll
        for (int off = 16; off > 0; off >>= 1)
            v += __shfl_down_sync(0xffffffffu, v, off);
        if (lane == 0) atomicAdd(&out[b], v);
    }
}

extern "C" void kernel_launch(void* const* d_in, const int* in_sizes, int n_in,
                              void* d_out, int out_size) {
    const float* x1 = (const float*)d_in[0];  // input1 [B,N,3]
    const float* x2 = (const float*)d_in[1];  // input2 [B,M,3]
    float* out = (float*)d_out;               // [B] float32

    k_init<<<(BB * NN + 255) / 256, 256>>>(out);

    static const float levels[10] = {
        -16384.f, -4096.f, -1024.f, -256.f, -64.f, -16.f, -4.f, -1.f, -0.25f, 0.f
    };

    dim3 grid(NN / RPC, BB);   // (16, 8)
    int cur = 0;
    for (int i = 0; i < 10; i++) {
        float q = levels[i] * LOG2E;
        bool sp = (levels[i] <= -64.0f);
        if (sp) {
            k_rowsum<true><<<grid, NT>>>(x1, x2, cur, q);
            k_colsum<true><<<grid, NT>>>(x1, x2, cur, q);
            k_pass3 <true><<<grid, NT>>>(x1, x2, cur, cur ^ 1, q, out);
        } else {
            k_rowsum<false><<<grid, NT>>>(x1, x2, cur, q);
            k_colsum<false><<<grid, NT>>>(x1, x2, cur, q);
            k_pass3 <false><<<grid, NT>>>(x1, x2, cur, cur ^ 1, q, out);
        }
        cur ^= 1;
    }
}

// round 5
// speedup vs baseline: 1.8235x; 1.2536x over previous
#include <cuda_runtime.h>

// EMD approx-match (auction annealing), B=8, N=M=2048, 3-D points.
// R4: fuse pass3(i) + rowsum(i+1) (reuse d2), hoist per-row factor F out of
// the exponent (scale partial sums instead), analytic collapse of level L=0.
// Launches: 31 -> 21.

#define BB 8
#define NN 2048
#define MM 2048
#define EPSF 1e-9f
#define LOG2E 1.4426950408889634f
#define TMIN -126.0f

#define NT   1024
#define RPC  128
#define SEGS 8
#define SEGL (MM / SEGS)   // 256

__device__ float g_s [BB * NN];
__device__ float g_ss[BB * MM];
__device__ float g_rL[2][BB * NN];
__device__ float g_rR[2][BB * MM];

__device__ __forceinline__ float lg2f(float x) {
    float r; asm("lg2.approx.f32 %0, %1;" : "=f"(r) : "f"(x)); return r;
}
__device__ __forceinline__ float ex2f(float x) {
    float r; asm("ex2.approx.f32 %0, %1;" : "=f"(r) : "f"(x)); return r;
}
__device__ __forceinline__ float sqrt_apx(float x) {
    float r; asm("sqrt.approx.f32 %0, %1;" : "=f"(r) : "f"(x)); return r;
}

__global__ void k_init(float* out) {
    int i = blockIdx.x * blockDim.x + threadIdx.x;
    if (i < BB * NN) { g_rL[0][i] = 1.0f; g_rR[0][i] = 1.0f; }
    if (i < BB) out[i] = 0.0f;
}

// ---------------- standalone rowsum (level 0 only, sparse) ----------------
__global__ void __launch_bounds__(NT, 1)
k_rowsum0(const float* __restrict__ x1, const float* __restrict__ x2, float q) {
    __shared__ float4 tile[MM];
    __shared__ float  red[NT];
    const int b   = blockIdx.y;
    const int tid = threadIdx.x;
    const float n2q = -2.0f * q;
    const float* __restrict__ rR = g_rR[0] + b * MM;

    for (int j = tid; j < MM; j += NT) {
        const float* yp = x2 + ((size_t)b * MM + j) * 3;
        float y0 = yp[0], y1 = yp[1], y2 = yp[2];
        float c  = fmaf(q, fmaf(y0, y0, fmaf(y1, y1, y2 * y2)), lg2f(rR[j]));
        tile[j] = make_float4(n2q * y0, n2q * y1, n2q * y2, c);
    }
    __syncthreads();

    const int r  = blockIdx.x * RPC + (tid & (RPC - 1));
    const int m0 = (tid >> 7) * SEGL;
    const float* xp = x1 + ((size_t)b * NN + r) * 3;
    float X0 = xp[0], X1 = xp[1], X2 = xp[2];
    float a  = q * fmaf(X0, X0, fmaf(X1, X1, X2 * X2));

    float s0 = 0.f, s1 = 0.f, s2 = 0.f, s3 = 0.f;
#pragma unroll 4
    for (int m = m0; m < m0 + SEGL; m += 4) {
        float4 P0 = tile[m + 0], P1 = tile[m + 1], P2 = tile[m + 2], P3 = tile[m + 3];
        float t0 = fmaf(X0, P0.x, fmaf(X1, P0.y, fmaf(X2, P0.z, a + P0.w)));
        float t1 = fmaf(X0, P1.x, fmaf(X1, P1.y, fmaf(X2, P1.z, a + P1.w)));
        float t2 = fmaf(X0, P2.x, fmaf(X1, P2.y, fmaf(X2, P2.z, a + P2.w)));
        float t3 = fmaf(X0, P3.x, fmaf(X1, P3.y, fmaf(X2, P3.z, a + P3.w)));
        float tm = fmaxf(fmaxf(t0, t1), fmaxf(t2, t3));
        if (__ballot_sync(0xffffffffu, tm > TMIN) != 0u) {
            s0 += ex2f(t0); s1 += ex2f(t1); s2 += ex2f(t2); s3 += ex2f(t3);
        }
    }
    red[tid] = (s0 + s1) + (s2 + s3);
    __syncthreads();
    if (tid < RPC) {
        float v = 0.f;
#pragma unroll
        for (int k = 0; k < SEGS; k++) v += red[tid + (k << 7)];
        g_s[(size_t)b * NN + blockIdx.x * RPC + tid] = v;
    }
}

// ---------------- colsum: ss[b][m] ----------------
template <bool SPARSE>
__global__ void __launch_bounds__(NT, 1)
k_colsum(const float* __restrict__ x1, const float* __restrict__ x2,
         int src, float q) {
    __shared__ float4 tile[NN];
    __shared__ float  red[NT];
    const int b   = blockIdx.y;
    const int tid = threadIdx.x;
    const float n2q = -2.0f * q;

    for (int j = tid; j < NN; j += NT) {
        const float* xp = x1 + ((size_t)b * NN + j) * 3;
        float a0 = xp[0], a1 = xp[1], a2 = xp[2];
        float rl = g_rL[src][(size_t)b * NN + j];
        float sv = g_s[(size_t)b * NN + j];
        float f  = __fdividef(rl, sv + EPSF);
        float aj = fmaf(q, fmaf(a0, a0, fmaf(a1, a1, a2 * a2)), lg2f(f));
        tile[j] = make_float4(n2q * a0, n2q * a1, n2q * a2, aj);
    }
    __syncthreads();

    const int mcol = blockIdx.x * RPC + (tid & (RPC - 1));
    const int n0   = (tid >> 7) * SEGL;
    const float* yp = x2 + ((size_t)b * MM + mcol) * 3;
    float Y0 = yp[0], Y1 = yp[1], Y2 = yp[2];
    float c  = fmaf(q, fmaf(Y0, Y0, fmaf(Y1, Y1, Y2 * Y2)),
                    lg2f(g_rR[src][(size_t)b * MM + mcol]));

    float s0 = 0.f, s1 = 0.f, s2 = 0.f, s3 = 0.f;
#pragma unroll 4
    for (int n = n0; n < n0 + SEGL; n += 4) {
        float4 P0 = tile[n + 0], P1 = tile[n + 1], P2 = tile[n + 2], P3 = tile[n + 3];
        float t0 = fmaf(Y0, P0.x, fmaf(Y1, P0.y, fmaf(Y2, P0.z, c + P0.w)));
        float t1 = fmaf(Y0, P1.x, fmaf(Y1, P1.y, fmaf(Y2, P1.z, c + P1.w)));
        float t2 = fmaf(Y0, P2.x, fmaf(Y1, P2.y, fmaf(Y2, P2.z, c + P2.w)));
        float t3 = fmaf(Y0, P3.x, fmaf(Y1, P3.y, fmaf(Y2, P3.z, c + P3.w)));
        bool go = true;
        if (SPARSE) {
            float tm = fmaxf(fmaxf(t0, t1), fmaxf(t2, t3));
            go = __ballot_sync(0xffffffffu, tm > TMIN) != 0u;
        }
        if (go) {
            s0 += ex2f(t0); s1 += ex2f(t1); s2 += ex2f(t2); s3 += ex2f(t3);
        }
    }
    red[tid] = (s0 + s1) + (s2 + s3);
    __syncthreads();
    if (tid < RPC) {
        float v = 0.f;
#pragma unroll
        for (int k = 0; k < SEGS; k++) v += red[tid + (k << 7)];
        g_ss[(size_t)b * MM + blockIdx.x * RPC + tid] = v;
    }
}

// ---------------- fused: pass3(level i) + rowsum(level i+1) ----------------
// Inner loop per pair: d2 (shared), level-i weight (unscaled by F), cost,
// rL partial, and next-level rowsum term exp2(q2*d2 + lg2 rR').
template <bool SP1, bool SP2>
__global__ void __launch_bounds__(NT, 1)
k_fused(const float* __restrict__ x1, const float* __restrict__ x2,
        int src, float q, float q2, float* __restrict__ out) {
    __shared__ float4 tile[MM];
    __shared__ __align__(16) float tile2[MM];
    __shared__ float  red[NT];
    __shared__ float  cwarp[NT / 32];
    const int b   = blockIdx.y;
    const int tid = threadIdx.x;
    const int lane = tid & 31;
    const int wid  = tid >> 5;
    const float* __restrict__ rR  = g_rR[src] + b * MM;
    float*       __restrict__ rRn = g_rR[src ^ 1] + b * MM;
    const float* __restrict__ ssp = g_ss + b * MM;

    for (int j = tid; j < MM; j += NT) {
        const float* yp = x2 + ((size_t)b * MM + j) * 3;
        float y0 = yp[0], y1 = yp[1], y2 = yp[2];
        float rr  = rR[j];
        float ssv = ssp[j];
        float ratio = fminf(__fdividef(rr, ssv + EPSF), 1.0f);
        tile[j] = make_float4(y0, y1, y2, lg2f(rr * ratio));
        float rrn = fmaxf(rr - ratio * ssv, 0.0f);
        tile2[j] = lg2f(rrn);
        if (blockIdx.x == 0) rRn[j] = rrn;   // exact identity, no pair pass
    }
    __syncthreads();

    const int r  = blockIdx.x * RPC + (tid & (RPC - 1));
    const int m0 = (tid >> 7) * SEGL;
    const float* xp = x1 + ((size_t)b * NN + r) * 3;
    float X0 = xp[0], X1 = xp[1], X2 = xp[2];
    float rl = g_rL[src][(size_t)b * NN + r];
    float sv = g_s[(size_t)b * NN + r];
    float F  = __fdividef(rl, sv + EPSF);   // hoisted per-row factor

    float rs0 = 0.f, rs1 = 0.f, c0 = 0.f, c1 = 0.f, sn0 = 0.f, sn1 = 0.f;
    const float4* __restrict__ t2v = (const float4*)tile2;
    for (int m = m0; m < m0 + SEGL; m += 4) {
        float4 P0 = tile[m + 0], P1 = tile[m + 1], P2 = tile[m + 2], P3 = tile[m + 3];
        float4 T  = t2v[m >> 2];
        float dx0 = X0 - P0.x, dy0 = X1 - P0.y, dz0 = X2 - P0.z;
        float dx1 = X0 - P1.x, dy1 = X1 - P1.y, dz1 = X2 - P1.z;
        float dx2 = X0 - P2.x, dy2 = X1 - P2.y, dz2 = X2 - P2.z;
        float dx3 = X0 - P3.x, dy3 = X1 - P3.y, dz3 = X2 - P3.z;
        float d20 = fmaf(dx0, dx0, fmaf(dy0, dy0, dz0 * dz0));
        float d21 = fmaf(dx1, dx1, fmaf(dy1, dy1, dz1 * dz1));
        float d22 = fmaf(dx2, dx2, fmaf(dy2, dy2, dz2 * dz2));
        float d23 = fmaf(dx3, dx3, fmaf(dy3, dy3, dz3 * dz3));
        float t0 = fmaf(d20, q, P0.w);
        float t1 = fmaf(d21, q, P1.w);
        float t2 = fmaf(d22, q, P2.w);
        float t3 = fmaf(d23, q, P3.w);
        bool go1 = true;
        if (SP1) {
            float tm = fmaxf(fmaxf(t0, t1), fmaxf(t2, t3));
            go1 = __ballot_sync(0xffffffffu, tm > TMIN) != 0u;
        }
        if (go1) {
            float w0 = ex2f(t0), w1 = ex2f(t1), w2 = ex2f(t2), w3 = ex2f(t3);
            rs0 += w0 + w2; rs1 += w1 + w3;
            c0 = fmaf(w0, sqrt_apx(d20), c0);
            c1 = fmaf(w1, sqrt_apx(d21), c1);
            c0 = fmaf(w2, sqrt_apx(d22), c0);
            c1 = fmaf(w3, sqrt_apx(d23), c1);
        }
        float u0 = fmaf(d20, q2, T.x);
        float u1 = fmaf(d21, q2, T.y);
        float u2 = fmaf(d22, q2, T.z);
        float u3 = fmaf(d23, q2, T.w);
        bool go2 = true;
        if (SP2) {
            float um = fmaxf(fmaxf(u0, u1), fmaxf(u2, u3));
            go2 = __ballot_sync(0xffffffffu, um > TMIN) != 0u;
        }
        if (go2) {
            sn0 += ex2f(u0) + ex2f(u2);
            sn1 += ex2f(u1) + ex2f(u3);
        }
    }

    // cost: scale by F per-thread (rows differ across lanes), shuffle reduce
    float c = (c0 + c1) * F;
#pragma unroll
    for (int off = 16; off > 0; off >>= 1)
        c += __shfl_down_sync(0xffffffffu, c, off);
    if (lane == 0) cwarp[wid] = c;

    // rL update (scale by F at the row owner)
    red[tid] = rs0 + rs1;
    __syncthreads();
    if (tid < RPC) {
        float v = 0.f;
#pragma unroll
        for (int k = 0; k < SEGS; k++) v += red[tid + (k << 7)];
        g_rL[src ^ 1][(size_t)b * NN + blockIdx.x * RPC + tid] =
            fmaxf(rl - v * F, 0.0f);   // tid<RPC ==> this thread owns row r=blk*RPC+tid, has rl,F
    }
    __syncthreads();
    // next-level rowsum
    red[tid] = sn0 + sn1;
    __syncthreads();
    if (tid < RPC) {
        float v = 0.f;
#pragma unroll
        for (int k = 0; k < SEGS; k++) v += red[tid + (k << 7)];
        g_s[(size_t)b * NN + blockIdx.x * RPC + tid] = v;
    }
    if (wid == 0) {
        float v = cwarp[lane];
#pragma unroll
        for (int off = 16; off > 0; off >>= 1)
            v += __shfl_down_sync(0xffffffffu, v, off);
        if (lane == 0) atomicAdd(&out[b], v);
    }
}

// ---------------- level 9 (L = 0): analytic s/ss, single cost pass ----------------
__global__ void __launch_bounds__(NT, 1)
k_last(const float* __restrict__ x1, const float* __restrict__ x2,
       int src, float* __restrict__ out) {
    __shared__ float4 tile[MM];
    __shared__ float  red[NT];
    __shared__ float  cwarp[NT / 32];
    __shared__ float  SLs;
    const int b   = blockIdx.y;
    const int tid = threadIdx.x;
    const int lane = tid & 31;
    const int wid  = tid >> 5;
    const float* __restrict__ rR = g_rR[src] + b * MM;
    const float* __restrict__ rL = g_rL[src] + b * NN;
    const float* __restrict__ sp = g_s + b * NN;   // s[n] = sum rR (from fused(8))

    // SL = sum_n rL[n]/(s[n]+eps)
    float acc = 0.f;
    for (int j = tid; j < NN; j += NT)
        acc += __fdividef(rL[j], sp[j] + EPSF);
    red[tid] = acc;
    __syncthreads();
    if (tid < 32) {
        float v = 0.f;
#pragma unroll
        for (int k = 0; k < NT / 32; k++) v += red[tid + k * 32];
#pragma unroll
        for (int off = 16; off > 0; off >>= 1)
            v += __shfl_down_sync(0xffffffffu, v, off);
        if (tid == 0) SLs = v;
    }
    __syncthreads();
    const float SL = SLs;

    // tile.w = rR[m]*ratio[m],  ratio = min(rR/(rR*SL+eps), 1)
    for (int j = tid; j < MM; j += NT) {
        const float* yp = x2 + ((size_t)b * MM + j) * 3;
        float rr = rR[j];
        float ratio = fminf(__fdividef(rr, fmaf(rr, SL, EPSF)), 1.0f);
        tile[j] = make_float4(yp[0], yp[1], yp[2], rr * ratio);
    }
    __syncthreads();

    const int r  = blockIdx.x * RPC + (tid & (RPC - 1));
    const int m0 = (tid >> 7) * SEGL;
    const float* xp = x1 + ((size_t)b * NN + r) * 3;
    float X0 = xp[0], X1 = xp[1], X2 = xp[2];
    float F = __fdividef(rL[r], sp[r] + EPSF);

    float c0 = 0.f, c1 = 0.f;
#pragma unroll 2
    for (int m = m0; m < m0 + SEGL; m += 2) {
        float4 P0 = tile[m + 0], P1 = tile[m + 1];
        float dx0 = X0 - P0.x, dy0 = X1 - P0.y, dz0 = X2 - P0.z;
        float dx1 = X0 - P1.x, dy1 = X1 - P1.y, dz1 = X2 - P1.z;
        float d20 = fmaf(dx0, dx0, fmaf(dy0, dy0, dz0 * dz0));
        float d21 = fmaf(dx1, dx1, fmaf(dy1, dy1, dz1 * dz1));
        c0 = fmaf(P0.w, sqrt_apx(d20), c0);
        c1 = fmaf(P1.w, sqrt_apx(d21), c1);
    }
    float c = (c0 + c1) * F;
#pragma unroll
    for (int off = 16; off > 0; off >>= 1)
        c += __shfl_down_sync(0xffffffffu, c, off);
    if (lane == 0) cwarp[wid] = c;
    __syncthreads();
    if (wid == 0) {
        float v = cwarp[lane];
#pragma unroll
        for (int off = 16; off > 0; off >>= 1)
            v += __shfl_down_sync(0xffffffffu, v, off);
        if (lane == 0) atomicAdd(&out[b], v);
    }
}

extern "C" void kernel_launch(void* const* d_in, const int* in_sizes, int n_in,
                              void* d_out, int out_size) {
    const float* x1 = (const float*)d_in[0];
    const float* x2 = (const float*)d_in[1];
    float* out = (float*)d_out;

    k_init<<<(BB * NN + 255) / 256, 256>>>(out);

    static const float levels[10] = {
        -16384.f, -4096.f, -1024.f, -256.f, -64.f, -16.f, -4.f, -1.f, -0.25f, 0.f
    };

    dim3 grid(NN / RPC, BB);   // (16, 8)
    int cur = 0;

    k_rowsum0<<<grid, NT>>>(x1, x2, levels[0] * LOG2E);

    for (int i = 0; i < 9; i++) {
        float q  = levels[i] * LOG2E;
        float q2 = levels[i + 1] * LOG2E;
        bool sp1 = (levels[i] <= -64.0f);
        bool sp2 = (levels[i + 1] <= -64.0f);
        if (sp1) k_colsum<true ><<<grid, NT>>>(x1, x2, cur, q);
        else     k_colsum<false><<<grid, NT>>>(x1, x2, cur, q);
        if (sp1 && sp2)       k_fused<true,  true ><<<grid, NT>>>(x1, x2, cur, q, q2, out);
        else if (sp1 && !sp2) k_fused<true,  false><<<grid, NT>>>(x1, x2, cur, q, q2, out);
        else                  k_fused<false, false><<<grid, NT>>>(x1, x2, cur, q, q2, out);
        cur ^= 1;
    }
    // level 9 (L=0): s/ss collapse analytically; one cost pass
    k_last<<<grid, NT>>>(x1, x2, cur, out);
}

// round 6
// speedup vs baseline: 1.8238x; 1.0002x over previous
#include <cuda_runtime.h>

// EMD approx-match (auction annealing), B=8, N=M=2048, 3-D points.
// R4: fuse pass3(i) + rowsum(i+1) (reuse d2), hoist per-row factor F out of
// the exponent (scale partial sums instead), analytic collapse of level L=0.
// Launches: 31 -> 21.

#define BB 8
#define NN 2048
#define MM 2048
#define EPSF 1e-9f
#define LOG2E 1.4426950408889634f
#define TMIN -126.0f

#define NT   1024
#define RPC  128
#define SEGS 8
#define SEGL (MM / SEGS)   // 256

__device__ float g_s [BB * NN];
__device__ float g_ss[BB * MM];
__device__ float g_rL[2][BB * NN];
__device__ float g_rR[2][BB * MM];

__device__ __forceinline__ float lg2f(float x) {
    float r; asm("lg2.approx.f32 %0, %1;" : "=f"(r) : "f"(x)); return r;
}
__device__ __forceinline__ float ex2f(float x) {
    float r; asm("ex2.approx.f32 %0, %1;" : "=f"(r) : "f"(x)); return r;
}
__device__ __forceinline__ float sqrt_apx(float x) {
    float r; asm("sqrt.approx.f32 %0, %1;" : "=f"(r) : "f"(x)); return r;
}

__global__ void k_init(float* out) {
    int i = blockIdx.x * blockDim.x + threadIdx.x;
    if (i < BB * NN) { g_rL[0][i] = 1.0f; g_rR[0][i] = 1.0f; }
    if (i < BB) out[i] = 0.0f;
}

// ---------------- standalone rowsum (level 0 only, sparse) ----------------
__global__ void __launch_bounds__(NT, 1)
k_rowsum0(const float* __restrict__ x1, const float* __restrict__ x2, float q) {
    __shared__ float4 tile[MM];
    __shared__ float  red[NT];
    const int b   = blockIdx.y;
    const int tid = threadIdx.x;
    const float n2q = -2.0f * q;
    const float* __restrict__ rR = g_rR[0] + b * MM;

    for (int j = tid; j < MM; j += NT) {
        const float* yp = x2 + ((size_t)b * MM + j) * 3;
        float y0 = yp[0], y1 = yp[1], y2 = yp[2];
        float c  = fmaf(q, fmaf(y0, y0, fmaf(y1, y1, y2 * y2)), lg2f(rR[j]));
        tile[j] = make_float4(n2q * y0, n2q * y1, n2q * y2, c);
    }
    __syncthreads();

    const int r  = blockIdx.x * RPC + (tid & (RPC - 1));
    const int m0 = (tid >> 7) * SEGL;
    const float* xp = x1 + ((size_t)b * NN + r) * 3;
    float X0 = xp[0], X1 = xp[1], X2 = xp[2];
    float a  = q * fmaf(X0, X0, fmaf(X1, X1, X2 * X2));

    float s0 = 0.f, s1 = 0.f, s2 = 0.f, s3 = 0.f;
#pragma unroll 4
    for (int m = m0; m < m0 + SEGL; m += 4) {
        float4 P0 = tile[m + 0], P1 = tile[m + 1], P2 = tile[m + 2], P3 = tile[m + 3];
        float t0 = fmaf(X0, P0.x, fmaf(X1, P0.y, fmaf(X2, P0.z, a + P0.w)));
        float t1 = fmaf(X0, P1.x, fmaf(X1, P1.y, fmaf(X2, P1.z, a + P1.w)));
        float t2 = fmaf(X0, P2.x, fmaf(X1, P2.y, fmaf(X2, P2.z, a + P2.w)));
        float t3 = fmaf(X0, P3.x, fmaf(X1, P3.y, fmaf(X2, P3.z, a + P3.w)));
        float tm = fmaxf(fmaxf(t0, t1), fmaxf(t2, t3));
        if (__ballot_sync(0xffffffffu, tm > TMIN) != 0u) {
            s0 += ex2f(t0); s1 += ex2f(t1); s2 += ex2f(t2); s3 += ex2f(t3);
        }
    }
    red[tid] = (s0 + s1) + (s2 + s3);
    __syncthreads();
    if (tid < RPC) {
        float v = 0.f;
#pragma unroll
        for (int k = 0; k < SEGS; k++) v += red[tid + (k << 7)];
        g_s[(size_t)b * NN + blockIdx.x * RPC + tid] = v;
    }
}

// ---------------- colsum: ss[b][m] ----------------
template <bool SPARSE>
__global__ void __launch_bounds__(NT, 1)
k_colsum(const float* __restrict__ x1, const float* __restrict__ x2,
         int src, float q) {
    __shared__ float4 tile[NN];
    __shared__ float  red[NT];
    const int b   = blockIdx.y;
    const int tid = threadIdx.x;
    const float n2q = -2.0f * q;

    for (int j = tid; j < NN; j += NT) {
        const float* xp = x1 + ((size_t)b * NN + j) * 3;
        float a0 = xp[0], a1 = xp[1], a2 = xp[2];
        float rl = g_rL[src][(size_t)b * NN + j];
        float sv = g_s[(size_t)b * NN + j];
        float f  = __fdividef(rl, sv + EPSF);
        float aj = fmaf(q, fmaf(a0, a0, fmaf(a1, a1, a2 * a2)), lg2f(f));
        tile[j] = make_float4(n2q * a0, n2q * a1, n2q * a2, aj);
    }
    __syncthreads();

    const int mcol = blockIdx.x * RPC + (tid & (RPC - 1));
    const int n0   = (tid >> 7) * SEGL;
    const float* yp = x2 + ((size_t)b * MM + mcol) * 3;
    float Y0 = yp[0], Y1 = yp[1], Y2 = yp[2];
    float c  = fmaf(q, fmaf(Y0, Y0, fmaf(Y1, Y1, Y2 * Y2)),
                    lg2f(g_rR[src][(size_t)b * MM + mcol]));

    float s0 = 0.f, s1 = 0.f, s2 = 0.f, s3 = 0.f;
#pragma unroll 4
    for (int n = n0; n < n0 + SEGL; n += 4) {
        float4 P0 = tile[n + 0], P1 = tile[n + 1], P2 = tile[n + 2], P3 = tile[n + 3];
        float t0 = fmaf(Y0, P0.x, fmaf(Y1, P0.y, fmaf(Y2, P0.z, c + P0.w)));
        float t1 = fmaf(Y0, P1.x, fmaf(Y1, P1.y, fmaf(Y2, P1.z, c + P1.w)));
        float t2 = fmaf(Y0, P2.x, fmaf(Y1, P2.y, fmaf(Y2, P2.z, c + P2.w)));
        float t3 = fmaf(Y0, P3.x, fmaf(Y1, P3.y, fmaf(Y2, P3.z, c + P3.w)));
        bool go = true;
        if (SPARSE) {
            float tm = fmaxf(fmaxf(t0, t1), fmaxf(t2, t3));
            go = __ballot_sync(0xffffffffu, tm > TMIN) != 0u;
        }
        if (go) {
            s0 += ex2f(t0); s1 += ex2f(t1); s2 += ex2f(t2); s3 += ex2f(t3);
        }
    }
    red[tid] = (s0 + s1) + (s2 + s3);
    __syncthreads();
    if (tid < RPC) {
        float v = 0.f;
#pragma unroll
        for (int k = 0; k < SEGS; k++) v += red[tid + (k << 7)];
        g_ss[(size_t)b * MM + blockIdx.x * RPC + tid] = v;
    }
}

// ---------------- fused: pass3(level i) + rowsum(level i+1) ----------------
// Inner loop per pair: d2 (shared), level-i weight (unscaled by F), cost,
// rL partial, and next-level rowsum term exp2(q2*d2 + lg2 rR').
template <bool SP1, bool SP2>
__global__ void __launch_bounds__(NT, 1)
k_fused(const float* __restrict__ x1, const float* __restrict__ x2,
        int src, float q, float q2, float* __restrict__ out) {
    __shared__ float4 tile[MM];
    __shared__ __align__(16) float tile2[MM];
    __shared__ float  red[NT];
    __shared__ float  cwarp[NT / 32];
    const int b   = blockIdx.y;
    const int tid = threadIdx.x;
    const int lane = tid & 31;
    const int wid  = tid >> 5;
    const float* __restrict__ rR  = g_rR[src] + b * MM;
    float*       __restrict__ rRn = g_rR[src ^ 1] + b * MM;
    const float* __restrict__ ssp = g_ss + b * MM;

    for (int j = tid; j < MM; j += NT) {
        const float* yp = x2 + ((size_t)b * MM + j) * 3;
        float y0 = yp[0], y1 = yp[1], y2 = yp[2];
        float rr  = rR[j];
        float ssv = ssp[j];
        float ratio = fminf(__fdividef(rr, ssv + EPSF), 1.0f);
        tile[j] = make_float4(y0, y1, y2, lg2f(rr * ratio));
        float rrn = fmaxf(rr - ratio * ssv, 0.0f);
        tile2[j] = lg2f(rrn);
        if (blockIdx.x == 0) rRn[j] = rrn;   // exact identity, no pair pass
    }
    __syncthreads();

    const int r  = blockIdx.x * RPC + (tid & (RPC - 1));
    const int m0 = (tid >> 7) * SEGL;
    const float* xp = x1 + ((size_t)b * NN + r) * 3;
    float X0 = xp[0], X1 = xp[1], X2 = xp[2];
    float rl = g_rL[src][(size_t)b * NN + r];
    float sv = g_s[(size_t)b * NN + r];
    float F  = __fdividef(rl, sv + EPSF);   // hoisted per-row factor

    float rs0 = 0.f, rs1 = 0.f, c0 = 0.f, c1 = 0.f, sn0 = 0.f, sn1 = 0.f;
    const float4* __restrict__ t2v = (const float4*)tile2;
    for (int m = m0; m < m0 + SEGL; m += 4) {
        float4 P0 = tile[m + 0], P1 = tile[m + 1], P2 = tile[m + 2], P3 = tile[m + 3];
        float4 T  = t2v[m >> 2];
        float dx0 = X0 - P0.x, dy0 = X1 - P0.y, dz0 = X2 - P0.z;
        float dx1 = X0 - P1.x, dy1 = X1 - P1.y, dz1 = X2 - P1.z;
        float dx2 = X0 - P2.x, dy2 = X1 - P2.y, dz2 = X2 - P2.z;
        float dx3 = X0 - P3.x, dy3 = X1 - P3.y, dz3 = X2 - P3.z;
        float d20 = fmaf(dx0, dx0, fmaf(dy0, dy0, dz0 * dz0));
        float d21 = fmaf(dx1, dx1, fmaf(dy1, dy1, dz1 * dz1));
        float d22 = fmaf(dx2, dx2, fmaf(dy2, dy2, dz2 * dz2));
        float d23 = fmaf(dx3, dx3, fmaf(dy3, dy3, dz3 * dz3));
        float t0 = fmaf(d20, q, P0.w);
        float t1 = fmaf(d21, q, P1.w);
        float t2 = fmaf(d22, q, P2.w);
        float t3 = fmaf(d23, q, P3.w);
        bool go1 = true;
        if (SP1) {
            float tm = fmaxf(fmaxf(t0, t1), fmaxf(t2, t3));
            go1 = __ballot_sync(0xffffffffu, tm > TMIN) != 0u;
        }
        if (go1) {
            float w0 = ex2f(t0), w1 = ex2f(t1), w2 = ex2f(t2), w3 = ex2f(t3);
            rs0 += w0 + w2; rs1 += w1 + w3;
            c0 = fmaf(w0, sqrt_apx(d20), c0);
            c1 = fmaf(w1, sqrt_apx(d21), c1);
            c0 = fmaf(w2, sqrt_apx(d22), c0);
            c1 = fmaf(w3, sqrt_apx(d23), c1);
        }
        float u0 = fmaf(d20, q2, T.x);
        float u1 = fmaf(d21, q2, T.y);
        float u2 = fmaf(d22, q2, T.z);
        float u3 = fmaf(d23, q2, T.w);
        bool go2 = true;
        if (SP2) {
            float um = fmaxf(fmaxf(u0, u1), fmaxf(u2, u3));
            go2 = __ballot_sync(0xffffffffu, um > TMIN) != 0u;
        }
        if (go2) {
            sn0 += ex2f(u0) + ex2f(u2);
            sn1 += ex2f(u1) + ex2f(u3);
        }
    }

    // cost: scale by F per-thread (rows differ across lanes), shuffle reduce
    float c = (c0 + c1) * F;
#pragma unroll
    for (int off = 16; off > 0; off >>= 1)
        c += __shfl_down_sync(0xffffffffu, c, off);
    if (lane == 0) cwarp[wid] = c;

    // rL update (scale by F at the row owner)
    red[tid] = rs0 + rs1;
    __syncthreads();
    if (tid < RPC) {
        float v = 0.f;
#pragma unroll
        for (int k = 0; k < SEGS; k++) v += red[tid + (k << 7)];
        g_rL[src ^ 1][(size_t)b * NN + blockIdx.x * RPC + tid] =
            fmaxf(rl - v * F, 0.0f);   // tid<RPC ==> this thread owns row r=blk*RPC+tid, has rl,F
    }
    __syncthreads();
    // next-level rowsum
    red[tid] = sn0 + sn1;
    __syncthreads();
    if (tid < RPC) {
        float v = 0.f;
#pragma unroll
        for (int k = 0; k < SEGS; k++) v += red[tid + (k << 7)];
        g_s[(size_t)b * NN + blockIdx.x * RPC + tid] = v;
    }
    if (wid == 0) {
        float v = cwarp[lane];
#pragma unroll
        for (int off = 16; off > 0; off >>= 1)
            v += __shfl_down_sync(0xffffffffu, v, off);
        if (lane == 0) atomicAdd(&out[b], v);
    }
}

// ---------------- level 9 (L = 0): analytic s/ss, single cost pass ----------------
__global__ void __launch_bounds__(NT, 1)
k_last(const float* __restrict__ x1, const float* __restrict__ x2,
       int src, float* __restrict__ out) {
    __shared__ float4 tile[MM];
    __shared__ float  red[NT];
    __shared__ float  cwarp[NT / 32];
    __shared__ float  SLs;
    const int b   = blockIdx.y;
    const int tid = threadIdx.x;
    const int lane = tid & 31;
    const int wid  = tid >> 5;
    const float* __restrict__ rR = g_rR[src] + b * MM;
    const float* __restrict__ rL = g_rL[src] + b * NN;
    const float* __restrict__ sp = g_s + b * NN;   // s[n] = sum rR (from fused(8))

    // SL = sum_n rL[n]/(s[n]+eps)
    float acc = 0.f;
    for (int j = tid; j < NN; j += NT)
        acc += __fdividef(rL[j], sp[j] + EPSF);
    red[tid] = acc;
    __syncthreads();
    if (tid < 32) {
        float v = 0.f;
#pragma unroll
        for (int k = 0; k < NT / 32; k++) v += red[tid + k * 32];
#pragma unroll
        for (int off = 16; off > 0; off >>= 1)
            v += __shfl_down_sync(0xffffffffu, v, off);
        if (tid == 0) SLs = v;
    }
    __syncthreads();
    const float SL = SLs;

    // tile.w = rR[m]*ratio[m],  ratio = min(rR/(rR*SL+eps), 1)
    for (int j = tid; j < MM; j += NT) {
        const float* yp = x2 + ((size_t)b * MM + j) * 3;
        float rr = rR[j];
        float ratio = fminf(__fdividef(rr, fmaf(rr, SL, EPSF)), 1.0f);
        tile[j] = make_float4(yp[0], yp[1], yp[2], rr * ratio);
    }
    __syncthreads();

    const int r  = blockIdx.x * RPC + (tid & (RPC - 1));
    const int m0 = (tid >> 7) * SEGL;
    const float* xp = x1 + ((size_t)b * NN + r) * 3;
    float X0 = xp[0], X1 = xp[1], X2 = xp[2];
    float F = __fdividef(rL[r], sp[r] + EPSF);

    float c0 = 0.f, c1 = 0.f;
#pragma unroll 2
    for (int m = m0; m < m0 + SEGL; m += 2) {
        float4 P0 = tile[m + 0], P1 = tile[m + 1];
        float dx0 = X0 - P0.x, dy0 = X1 - P0.y, dz0 = X2 - P0.z;
        float dx1 = X0 - P1.x, dy1 = X1 - P1.y, dz1 = X2 - P1.z;
        float d20 = fmaf(dx0, dx0, fmaf(dy0, dy0, dz0 * dz0));
        float d21 = fmaf(dx1, dx1, fmaf(dy1, dy1, dz1 * dz1));
        c0 = fmaf(P0.w, sqrt_apx(d20), c0);
        c1 = fmaf(P1.w, sqrt_apx(d21), c1);
    }
    float c = (c0 + c1) * F;
#pragma unroll
    for (int off = 16; off > 0; off >>= 1)
        c += __shfl_down_sync(0xffffffffu, c, off);
    if (lane == 0) cwarp[wid] = c;
    __syncthreads();
    if (wid == 0) {
        float v = cwarp[lane];
#pragma unroll
        for (int off = 16; off > 0; off >>= 1)
            v += __shfl_down_sync(0xffffffffu, v, off);
        if (lane == 0) atomicAdd(&out[b], v);
    }
}

extern "C" void kernel_launch(void* const* d_in, const int* in_sizes, int n_in,
                              void* d_out, int out_size) {
    const float* x1 = (const float*)d_in[0];
    const float* x2 = (const float*)d_in[1];
    float* out = (float*)d_out;

    k_init<<<(BB * NN + 255) / 256, 256>>>(out);

    static const float levels[10] = {
        -16384.f, -4096.f, -1024.f, -256.f, -64.f, -16.f, -4.f, -1.f, -0.25f, 0.f
    };

    dim3 grid(NN / RPC, BB);   // (16, 8)
    int cur = 0;

    k_rowsum0<<<grid, NT>>>(x1, x2, levels[0] * LOG2E);

    for (int i = 0; i < 9; i++) {
        float q  = levels[i] * LOG2E;
        float q2 = levels[i + 1] * LOG2E;
        bool sp1 = (levels[i] <= -64.0f);
        bool sp2 = (levels[i + 1] <= -64.0f);
        if (sp1) k_colsum<true ><<<grid, NT>>>(x1, x2, cur, q);
        else     k_colsum<false><<<grid, NT>>>(x1, x2, cur, q);
        if (sp1 && sp2)       k_fused<true,  true ><<<grid, NT>>>(x1, x2, cur, q, q2, out);
        else if (sp1 && !sp2) k_fused<true,  false><<<grid, NT>>>(x1, x2, cur, q, q2, out);
        else                  k_fused<false, false><<<grid, NT>>>(x1, x2, cur, q, q2, out);
        cur ^= 1;
    }
    // level 9 (L=0): s/ss collapse analytically; one cost pass
    k_last<<<grid, NT>>>(x1, x2, cur, out);
}